// round 2
// baseline (speedup 1.0000x reference)
#include <cuda_runtime.h>
#include <cstdint>

#define BATCH   2
#define SEQ     2048
#define DMODEL  1024
#define NHEADS  16
#define DHEAD   64
#define N3      3072
#define MROWS   (BATCH * SEQ)

// scratch: [part(3)][b(2)][h(16)][s(2048)][dh(64)]
__device__ float g_qkv[3u * BATCH * NHEADS * SEQ * DHEAD];

typedef unsigned long long u64;

__device__ __forceinline__ u64 pack2(float x, float y) {
    u64 r; asm("mov.b64 %0, {%1, %2};" : "=l"(r) : "f"(x), "f"(y)); return r;
}
__device__ __forceinline__ float2 unpack2(u64 v) {
    float2 r; asm("mov.b64 {%0, %1}, %2;" : "=f"(r.x), "=f"(r.y) : "l"(v)); return r;
}
__device__ __forceinline__ void fma2(u64& d, u64 a, u64 b) {
    asm("fma.rn.f32x2 %0, %1, %2, %0;" : "+l"(d) : "l"(a), "l"(b));
}
__device__ __forceinline__ void mul2(u64& d, u64 a) {
    asm("mul.rn.f32x2 %0, %0, %1;" : "+l"(d) : "l"(a));
}

// ---------------------------------------------------------------------------
// QKV GEMM: C[4096,3072] = x @ W + b, scattered into g_qkv
// ---------------------------------------------------------------------------
__global__ __launch_bounds__(256) void qkv_gemm(const float* __restrict__ x,
                                                const float* __restrict__ W,
                                                const float* __restrict__ bias) {
    __shared__ float As[16][128];
    __shared__ float Bs[16][128];

    const int t  = threadIdx.x;
    const int tx = t & 15, ty = t >> 4;
    const int n0 = blockIdx.x * 128;
    const int m0 = blockIdx.y * 128;

    const int alr = t >> 2,  alc  = (t & 3) << 2;
    const int brw = t >> 5,  bcl  = (t & 31) << 2;

    u64 acc[8][4] = {};

    for (int k0 = 0; k0 < DMODEL; k0 += 16) {
        float4 a0 = *(const float4*)&x[(size_t)(m0 + alr)      * DMODEL + k0 + alc];
        float4 a1 = *(const float4*)&x[(size_t)(m0 + alr + 64) * DMODEL + k0 + alc];
        float4 b0 = *(const float4*)&W[(size_t)(k0 + brw)     * N3 + n0 + bcl];
        float4 b1 = *(const float4*)&W[(size_t)(k0 + brw + 8) * N3 + n0 + bcl];
        __syncthreads();
        As[alc + 0][alr] = a0.x; As[alc + 1][alr] = a0.y;
        As[alc + 2][alr] = a0.z; As[alc + 3][alr] = a0.w;
        As[alc + 0][alr + 64] = a1.x; As[alc + 1][alr + 64] = a1.y;
        As[alc + 2][alr + 64] = a1.z; As[alc + 3][alr + 64] = a1.w;
        *(float4*)&Bs[brw][bcl]     = b0;
        *(float4*)&Bs[brw + 8][bcl] = b1;
        __syncthreads();

#pragma unroll
        for (int k = 0; k < 16; k++) {
            float4 af0 = *(const float4*)&As[k][ty * 8];
            float4 af1 = *(const float4*)&As[k][ty * 8 + 4];
            ulonglong2 bv0 = *(const ulonglong2*)&Bs[k][tx * 8];
            ulonglong2 bv1 = *(const ulonglong2*)&Bs[k][tx * 8 + 4];
            float a[8] = {af0.x, af0.y, af0.z, af0.w, af1.x, af1.y, af1.z, af1.w};
#pragma unroll
            for (int i = 0; i < 8; i++) {
                u64 a2 = pack2(a[i], a[i]);
                fma2(acc[i][0], a2, bv0.x);
                fma2(acc[i][1], a2, bv0.y);
                fma2(acc[i][2], a2, bv1.x);
                fma2(acc[i][3], a2, bv1.y);
            }
        }
    }

    const int col0 = n0 + tx * 8;
    const int part = col0 >> 10;
    const int h    = (col0 >> 6) & 15;
    const int dh0  = col0 & 63;
    float bs[8];
#pragma unroll
    for (int j = 0; j < 8; j++) bs[j] = bias[col0 + j];

#pragma unroll
    for (int i = 0; i < 8; i++) {
        int row = m0 + ty * 8 + i;
        int bb = row >> 11, s = row & 2047;
        float* dst = g_qkv + ((size_t)((part * 2 + bb) * NHEADS + h) * SEQ + s) * DHEAD + dh0;
        float2 u0 = unpack2(acc[i][0]), u1 = unpack2(acc[i][1]);
        float2 u2 = unpack2(acc[i][2]), u3 = unpack2(acc[i][3]);
        *(float4*)&dst[0] = make_float4(u0.x + bs[0], u0.y + bs[1], u1.x + bs[2], u1.y + bs[3]);
        *(float4*)&dst[4] = make_float4(u2.x + bs[4], u2.y + bs[5], u3.x + bs[6], u3.y + bs[7]);
    }
}

// ---------------------------------------------------------------------------
// Flash attention: 64-query block per CTA, 256 threads (16x16), 4x4 micro.
// ---------------------------------------------------------------------------
__global__ __launch_bounds__(256) void attn_kernel(float* __restrict__ out) {
    __shared__ float Qs[64 * 64];
    __shared__ float KV[64 * 64];
    __shared__ float Ps[64 * 64];

    const int t  = threadIdx.x;
    const int tx = t & 15, ty = t >> 4;
    const int q0 = blockIdx.x * 64;
    const int h  = blockIdx.y;
    const int bb = blockIdx.z;

    const float* Qg = g_qkv + (size_t)((0 * 2 + bb) * NHEADS + h) * (SEQ * DHEAD);
    const float* Kg = g_qkv + (size_t)((1 * 2 + bb) * NHEADS + h) * (SEQ * DHEAD);
    const float* Vg = g_qkv + (size_t)((2 * 2 + bb) * NHEADS + h) * (SEQ * DHEAD);

#pragma unroll
    for (int i = t; i < 1024; i += 256) {
        int r = i >> 4, c4 = (i & 15) << 2;
        *(float4*)&Qs[r * 64 + c4] = *(const float4*)&Qg[(size_t)(q0 + r) * 64 + c4];
    }

    u64 o2[4][2] = {};
    float m_i[4], l_i[4];
#pragma unroll
    for (int i = 0; i < 4; i++) { m_i[i] = -1e30f; l_i[i] = 0.f; }

    for (int kt = 0; kt < SEQ / 64; kt++) {
        const int k0 = kt * 64;
        __syncthreads();   // prior iteration done with KV (as V) and Ps

        // K tile, transposed + XOR-swizzled: (d, kk) -> KV[d*64 + 4*((kk>>2)^(d&15)) + (kk&3)]
        {
            int r = t >> 2, cb = t & 3;
#pragma unroll
            for (int it = 0; it < 4; it++) {
                int c4 = cb + (it << 2);
                float4 v = *(const float4*)&Kg[(size_t)(k0 + r) * 64 + (c4 << 2)];
                float vv[4] = {v.x, v.y, v.z, v.w};
#pragma unroll
                for (int j = 0; j < 4; j++) {
                    int d = (c4 << 2) + j;
                    int col = (r >> 2) ^ (d & 15);
                    KV[d * 64 + (col << 2) + (r & 3)] = vv[j];
                }
            }
        }
        __syncthreads();

        // S = Q @ K^T
        u64 s2[4][2] = {};
#pragma unroll 4
        for (int d = 0; d < 64; d++) {
            ulonglong2 kf = *(const ulonglong2*)&KV[d * 64 + ((tx ^ (d & 15)) << 2)];
#pragma unroll
            for (int i = 0; i < 4; i++) {
                float q = Qs[(4 * ty + i) * 64 + d];
                u64 q2 = pack2(q, q);
                fma2(s2[i][0], q2, kf.x);
                fma2(s2[i][1], q2, kf.y);
            }
        }

        // online softmax across the 16 tx lanes (one row = 64 keys)
        float p[4][4];
#pragma unroll
        for (int i = 0; i < 4; i++) {
            float2 u0 = unpack2(s2[i][0]), u1 = unpack2(s2[i][1]);
            p[i][0] = u0.x * 0.125f; p[i][1] = u0.y * 0.125f;
            p[i][2] = u1.x * 0.125f; p[i][3] = u1.y * 0.125f;
            float mt = fmaxf(fmaxf(p[i][0], p[i][1]), fmaxf(p[i][2], p[i][3]));
            mt = fmaxf(mt, __shfl_xor_sync(0xffffffffu, mt, 1));
            mt = fmaxf(mt, __shfl_xor_sync(0xffffffffu, mt, 2));
            mt = fmaxf(mt, __shfl_xor_sync(0xffffffffu, mt, 4));
            mt = fmaxf(mt, __shfl_xor_sync(0xffffffffu, mt, 8));
            float mn = fmaxf(m_i[i], mt);
            float sc = __expf(m_i[i] - mn);
            m_i[i] = mn;
            float ls = 0.f;
#pragma unroll
            for (int j = 0; j < 4; j++) { p[i][j] = __expf(p[i][j] - mn); ls += p[i][j]; }
            ls += __shfl_xor_sync(0xffffffffu, ls, 1);
            ls += __shfl_xor_sync(0xffffffffu, ls, 2);
            ls += __shfl_xor_sync(0xffffffffu, ls, 4);
            ls += __shfl_xor_sync(0xffffffffu, ls, 8);
            l_i[i] = l_i[i] * sc + ls;
            u64 sc2 = pack2(sc, sc);
            mul2(o2[i][0], sc2);
            mul2(o2[i][1], sc2);
        }
        __syncthreads();   // done reading KV as K

        // P -> smem; V -> KV (natural [kk][d])
#pragma unroll
        for (int i = 0; i < 4; i++)
            *(float4*)&Ps[(4 * ty + i) * 64 + (tx << 2)] =
                make_float4(p[i][0], p[i][1], p[i][2], p[i][3]);
#pragma unroll
        for (int i = t; i < 1024; i += 256) {
            int r = i >> 4, c4 = (i & 15) << 2;
            *(float4*)&KV[r * 64 + c4] = *(const float4*)&Vg[(size_t)(k0 + r) * 64 + c4];
        }
        __syncthreads();

        // O += P @ V
#pragma unroll 4
        for (int kk = 0; kk < 64; kk++) {
            ulonglong2 vf = *(const ulonglong2*)&KV[kk * 64 + (tx << 2)];
#pragma unroll
            for (int i = 0; i < 4; i++) {
                float pv = Ps[(4 * ty + i) * 64 + kk];
                u64 p2 = pack2(pv, pv);
                fma2(o2[i][0], p2, vf.x);
                fma2(o2[i][1], p2, vf.y);
            }
        }
    }

    // normalize + write out[b][s][h*64+dh]
#pragma unroll
    for (int i = 0; i < 4; i++) {
        float inv = 1.0f / l_i[i];
        int q = q0 + 4 * ty + i;
        float* dst = out + ((size_t)bb * SEQ + q) * DMODEL + h * DHEAD + (tx << 2);
        float2 u0 = unpack2(o2[i][0]), u1 = unpack2(o2[i][1]);
        *(float4*)dst = make_float4(u0.x * inv, u0.y * inv, u1.x * inv, u1.y * inv);
    }
}

extern "C" void kernel_launch(void* const* d_in, const int* in_sizes, int n_in,
                              void* d_out, int out_size) {
    const float* x    = (const float*)d_in[0];
    const float* W    = (const float*)d_in[1];
    const float* bias = (const float*)d_in[2];
    float* out = (float*)d_out;

    dim3 ggrid(N3 / 128, MROWS / 128);
    qkv_gemm<<<ggrid, 256>>>(x, W, bias);

    dim3 agrid(SEQ / 64, NHEADS, BATCH);
    attn_kernel<<<agrid, 256>>>(out);
}